// round 4
// baseline (speedup 1.0000x reference)
#include <cuda_runtime.h>
#include <cuda_bf16.h>
#include <cstdint>

#define Bv   16
#define Sv   128
#define Tv   128
#define Hv   1024
#define HIDv 512
#define Vv   32000
#define NBLK 128

// ---------------- device scratch (static; no allocations) ----------------
__device__ float g_xbuf0[Bv*Sv*Hv];
__device__ float g_xbuf1[Bv*Sv*Hv];
__device__ float g_gatesin[2*Bv*Sv*2048];      // [dir][b*S+s][2048]
__device__ float g_WhhEncT[2*2*HIDv*2048];     // [l*2+d][k=512][2048]
__device__ float g_henc[2*Bv*HIDv];
__device__ float g_cenc[2*Bv*HIDv];
__device__ float g_epart[2*8*Bv*2048];         // [d*8+kc][b][2048]
__device__ float g_hdec[2*Bv*Hv];
__device__ float g_cdec[2*Bv*Hv];
__device__ float g_demb[Bv*Tv*Hv];
__device__ float g_preL0[Bv*Tv*4096];
__device__ float g_WdecT0[2048*4096];          // [Wih0(op cols)^T ; Whh0^T]
__device__ float g_WdecT1[2048*4096];          // [Wih1^T ; Whh1^T]
__device__ float g_lininT[Hv*Hv];
__device__ float g_linoutT[2*Hv*Hv];
__device__ float g_op[Bv*Hv];
__device__ float g_cc[Bv*Hv];
__device__ float g_part0[8*Bv*4096];
__device__ float g_part1[8*Bv*4096];
__device__ float g_q[Bv*Hv];
__device__ float g_lopart[32*Bv*Hv];
__device__ float g_opn[Bv*Tv*Hv];

// grid barrier state (zero-initialized at module load; self-restoring)
__device__ unsigned g_barA;
__device__ unsigned g_barG;

// ---------------- helpers ----------------
__device__ __forceinline__ float2 ffma2(float2 a, float2 b, float2 c) {
    unsigned long long ra = *reinterpret_cast<unsigned long long*>(&a);
    unsigned long long rb = *reinterpret_cast<unsigned long long*>(&b);
    unsigned long long rc = *reinterpret_cast<unsigned long long*>(&c);
    unsigned long long rd;
    asm("fma.rn.f32x2 %0, %1, %2, %3;" : "=l"(rd) : "l"(ra), "l"(rb), "l"(rc));
    return *reinterpret_cast<float2*>(&rd);
}
__device__ __forceinline__ float sigf(float x) { return 1.0f / (1.0f + expf(-x)); }

// software grid barrier: all blocks must call; requires grid co-residency
__device__ __forceinline__ void gridbar() {
    __threadfence();            // make this thread's writes visible device-wide
    __syncthreads();
    if (threadIdx.x == 0) {
        unsigned gen = ((volatile unsigned*)&g_barG)[0];
        unsigned prev = atomicAdd(&g_barA, 1u);
        if (prev == gridDim.x - 1) {
            g_barA = 0;
            __threadfence();
            atomicExch(&g_barG, gen + 1);
        } else {
            while (((volatile unsigned*)&g_barG)[0] == gen) { }
        }
    }
    __syncthreads();
}

// ---------------- small kernels ----------------
// out[c][r] = in[r][col0 + c]
__global__ void k_transpose(const float* __restrict__ in, float* __restrict__ out,
                            int R, int C, int ld_in, int col0) {
    __shared__ float tile[32][33];
    int rb = blockIdx.y * 32, cb = blockIdx.x * 32;
    #pragma unroll
    for (int i = 0; i < 32; i += 8) {
        int r = rb + threadIdx.y + i, c = cb + threadIdx.x;
        if (r < R && c < C)
            tile[threadIdx.y + i][threadIdx.x] = in[(size_t)r * ld_in + col0 + c];
    }
    __syncthreads();
    #pragma unroll
    for (int i = 0; i < 32; i += 8) {
        int c = cb + threadIdx.y + i, r = rb + threadIdx.x;
        if (c < C && r < R)
            out[(size_t)c * R + r] = tile[threadIdx.x][threadIdx.y + i];
    }
}

__global__ void k_embed_enc(const float* __restrict__ emb, const int* __restrict__ inp,
                            float* __restrict__ x) {
    int i = blockIdx.x * blockDim.x + threadIdx.x;
    if (i >= Bv*Sv*Hv) return;
    int h = i & (Hv-1);
    int tok = i >> 10;
    x[i] = emb[(size_t)inp[tok] * Hv + h];
}

__global__ void k_embed_dec(const float* __restrict__ emb, const int* __restrict__ outtok,
                            float* __restrict__ demb) {
    int i = blockIdx.x * blockDim.x + threadIdx.x;
    if (i >= Bv*Tv*Hv) return;
    int h = i & (Hv-1);
    int bt = i >> 10;
    int b = bt >> 7, t = bt & 127;
    int id = (t == 0) ? 3 : outtok[b*Tv + t - 1];
    demb[i] = emb[(size_t)id * Hv + h];
}

// ---------------- tiled GEMM: C[M][N] = A[M][K] @ W[N][K]^T + bias[N] ----------------
__global__ void __launch_bounds__(256) k_gemm(
    const float* __restrict__ A, int lda,
    const float* __restrict__ W, int ldw,
    const float* __restrict__ bias,
    float* __restrict__ C, int ldc, int K) {
    __shared__ float As[16][132];
    __shared__ float Bs[16][132];
    int tid = threadIdx.x;
    int tx = tid & 15, ty = tid >> 4;
    size_t mb = (size_t)blockIdx.y * 128;
    size_t nb = (size_t)blockIdx.x * 128;
    float2 acc[8][4];
    #pragma unroll
    for (int i = 0; i < 8; i++)
        #pragma unroll
        for (int j = 0; j < 4; j++) acc[i][j] = make_float2(0.f, 0.f);

    int lr = tid >> 2;
    int lc4 = (tid & 3) * 4;
    const float* Ap  = A + (mb + lr) * (size_t)lda + lc4;
    const float* Ap2 = Ap + (size_t)64 * lda;
    const float* Wp  = W + (nb + lr) * (size_t)ldw + lc4;
    const float* Wp2 = Wp + (size_t)64 * ldw;

    for (int k0 = 0; k0 < K; k0 += 16) {
        float4 a0 = *(const float4*)(Ap  + k0);
        float4 a1 = *(const float4*)(Ap2 + k0);
        float4 b0 = *(const float4*)(Wp  + k0);
        float4 b1 = *(const float4*)(Wp2 + k0);
        As[lc4+0][lr] = a0.x; As[lc4+1][lr] = a0.y; As[lc4+2][lr] = a0.z; As[lc4+3][lr] = a0.w;
        As[lc4+0][lr+64] = a1.x; As[lc4+1][lr+64] = a1.y; As[lc4+2][lr+64] = a1.z; As[lc4+3][lr+64] = a1.w;
        Bs[lc4+0][lr] = b0.x; Bs[lc4+1][lr] = b0.y; Bs[lc4+2][lr] = b0.z; Bs[lc4+3][lr] = b0.w;
        Bs[lc4+0][lr+64] = b1.x; Bs[lc4+1][lr+64] = b1.y; Bs[lc4+2][lr+64] = b1.z; Bs[lc4+3][lr+64] = b1.w;
        __syncthreads();
        #pragma unroll
        for (int kk = 0; kk < 16; kk++) {
            float4 av0 = *(const float4*)&As[kk][ty*8];
            float4 av1 = *(const float4*)&As[kk][ty*8+4];
            float4 bv0 = *(const float4*)&Bs[kk][tx*8];
            float4 bv1 = *(const float4*)&Bs[kk][tx*8+4];
            float a8[8] = {av0.x,av0.y,av0.z,av0.w,av1.x,av1.y,av1.z,av1.w};
            float2 bp[4];
            bp[0] = make_float2(bv0.x, bv0.y); bp[1] = make_float2(bv0.z, bv0.w);
            bp[2] = make_float2(bv1.x, bv1.y); bp[3] = make_float2(bv1.z, bv1.w);
            #pragma unroll
            for (int i = 0; i < 8; i++) {
                float2 ai = make_float2(a8[i], a8[i]);
                #pragma unroll
                for (int j = 0; j < 4; j++) acc[i][j] = ffma2(ai, bp[j], acc[i][j]);
            }
        }
        __syncthreads();
    }
    float bsv[8];
    #pragma unroll
    for (int j = 0; j < 8; j++) bsv[j] = bias[nb + tx*8 + j];
    #pragma unroll
    for (int i = 0; i < 8; i++) {
        size_t row = mb + ty*8 + i;
        float* Cp = C + row * (size_t)ldc + nb + tx*8;
        float4 o0, o1;
        o0.x = acc[i][0].x + bsv[0]; o0.y = acc[i][0].y + bsv[1];
        o0.z = acc[i][1].x + bsv[2]; o0.w = acc[i][1].y + bsv[3];
        o1.x = acc[i][2].x + bsv[4]; o1.y = acc[i][2].y + bsv[5];
        o1.z = acc[i][3].x + bsv[6]; o1.w = acc[i][3].y + bsv[7];
        *(float4*)Cp = o0;
        *(float4*)(Cp + 4) = o1;
    }
}

// ---------------- persistent encoder layer: 128 blocks x 256 threads ----------------
__global__ void __launch_bounds__(256) k_enc_persist(
    const float* __restrict__ WhhT,       // [2][512][2048] (this layer)
    const float* __restrict__ gatesin,    // [2][2048][2048]
    float* __restrict__ h, float* __restrict__ c,   // [2][16][512]
    float* __restrict__ xout,             // [16][128][1024]
    float* __restrict__ epart,            // [16][16][2048]
    float* __restrict__ hd_slot, float* __restrict__ cd_slot) {
    __shared__ float sbuf[1024];
    int tid = threadIdx.x, bid = blockIdx.x;
    int gi = bid * 256 + tid;

    if (gi < 2*16*512) { h[gi] = 0.f; c[gi] = 0.f; }
    gridbar();

    int d  = bid >> 6;
    int nc = (bid >> 3) & 7;
    int kc = bid & 7;
    int kbase = kc * 64;
    int n = nc * 256 + tid;
    const float* hv = h + d * 16 * 512;
    const float* wp = WhhT + (size_t)d * 512 * 2048 + (size_t)kbase * 2048 + n;
    float* pp = epart + (size_t)((d*8 + kc) * 16) * 2048 + n;

    for (int s = 0; s < 128; s++) {
        // ---- gemv phase ----
        for (int i = tid; i < 64*16; i += 256) {
            int k = i >> 4, b = i & 15;
            sbuf[i] = hv[b*512 + kbase + k];
        }
        __syncthreads();
        {
            const float2* vs2 = (const float2*)sbuf;
            float2 acc[8];
            #pragma unroll
            for (int bp = 0; bp < 8; bp++) acc[bp] = make_float2(0.f, 0.f);
            #pragma unroll 8
            for (int k = 0; k < 64; k++) {
                float w = wp[(size_t)k * 2048];
                float2 w2 = make_float2(w, w);
                #pragma unroll
                for (int bp = 0; bp < 8; bp++) acc[bp] = ffma2(w2, vs2[k*8+bp], acc[bp]);
            }
            #pragma unroll
            for (int bp = 0; bp < 8; bp++) {
                pp[(size_t)(2*bp)   * 2048] = acc[bp].x;
                pp[(size_t)(2*bp+1) * 2048] = acc[bp].y;
            }
        }
        gridbar();
        // ---- cell phase ----
        if (gi < 16384) {
            int dd = gi >> 13, j = gi & 8191;
            int b = j >> 9, hh = j & 511;
            int sdir = dd ? (127 - s) : s;
            const float* gin = gatesin + ((size_t)dd*2048 + b*128 + sdir) * 2048;
            float g4[4];
            #pragma unroll
            for (int q4 = 0; q4 < 4; q4++) {
                int nn = q4*512 + hh;
                float v = gin[nn];
                #pragma unroll
                for (int k2 = 0; k2 < 8; k2++)
                    v += epart[(size_t)((dd*8 + k2)*16 + b)*2048 + nn];
                g4[q4] = v;
            }
            int idx = (dd*16 + b)*512 + hh;
            float cn = sigf(g4[1]) * c[idx] + sigf(g4[0]) * tanhf(g4[2]);
            float hn = sigf(g4[3]) * tanhf(cn);
            c[idx] = cn; h[idx] = hn;
            xout[((size_t)b*128 + sdir)*1024 + dd*512 + hh] = hn;
        }
        gridbar();
    }
    // ---- init decoder state from final h/c ----
    if (gi < 16384) {
        int b = gi >> 10, hh = gi & 1023;
        float hv2, cv2;
        if (hh < 512) { hv2 = h[b*512 + hh];            cv2 = c[b*512 + hh]; }
        else          { hv2 = h[(16+b)*512 + hh - 512]; cv2 = c[(16+b)*512 + hh - 512]; }
        hd_slot[b*1024 + hh] = hv2;
        cd_slot[b*1024 + hh] = cv2;
    }
}

// ---------------- persistent decoder: 128 blocks x 256 threads ----------------
__global__ void __launch_bounds__(256) k_dec_persist(
    const float* __restrict__ WdecT0, const float* __restrict__ WdecT1,
    const float* __restrict__ lininT, const float* __restrict__ linoutT,
    const float* __restrict__ preL0, const float* __restrict__ bias1,
    const float* __restrict__ enc,
    float* __restrict__ op,
    float* __restrict__ hd0, float* __restrict__ cd0,
    float* __restrict__ hd1, float* __restrict__ cd1,
    float* __restrict__ part0, float* __restrict__ part1,
    float* __restrict__ q, float* __restrict__ ccv,
    float* __restrict__ lopart, float* __restrict__ opn) {
    __shared__ float sbuf[4096];
    int tid = threadIdx.x, bid = blockIdx.x;
    int gi = bid * 256 + tid;

    if (gi < 16*1024) op[gi] = 0.f;
    gridbar();

    int ncA = bid >> 3, kcA = bid & 7;          // phase A/C partition
    int kbaseA = kcA * 256;
    int nA = ncA * 256 + tid;
    int ncG = bid >> 5, kcG = bid & 31;         // phase G partition
    int kbaseG = kcG * 64;
    int nG = ncG * 256 + tid;

    for (int t = 0; t < 128; t++) {
        // ---- Phase A: layer0 gate partials from [op, hd0] ----
        for (int i = tid; i < 256*16; i += 256) {
            int k = i >> 4, b = i & 15, kg = kbaseA + k;
            sbuf[i] = (kg < 1024) ? op[b*1024 + kg] : hd0[b*1024 + kg - 1024];
        }
        __syncthreads();
        {
            const float2* vs2 = (const float2*)sbuf;
            float2 acc[8];
            #pragma unroll
            for (int bp = 0; bp < 8; bp++) acc[bp] = make_float2(0.f, 0.f);
            const float* wp = WdecT0 + (size_t)kbaseA * 4096 + nA;
            #pragma unroll 8
            for (int k = 0; k < 256; k++) {
                float w = wp[(size_t)k * 4096];
                float2 w2 = make_float2(w, w);
                #pragma unroll
                for (int bp = 0; bp < 8; bp++) acc[bp] = ffma2(w2, vs2[k*8+bp], acc[bp]);
            }
            float* pp = part0 + (size_t)(kcA*16) * 4096 + nA;
            #pragma unroll
            for (int bp = 0; bp < 8; bp++) {
                pp[(size_t)(2*bp)   * 4096] = acc[bp].x;
                pp[(size_t)(2*bp+1) * 4096] = acc[bp].y;
            }
        }
        gridbar();
        // ---- Phase B: cell0 ----
        if (gi < 16384) {
            int b = gi >> 10, hh = gi & 1023;
            const float* pl = preL0 + ((size_t)b*128 + t) * 4096;
            float g4[4];
            #pragma unroll
            for (int q4 = 0; q4 < 4; q4++) {
                int n = q4*1024 + hh;
                float v = pl[n];
                #pragma unroll
                for (int k2 = 0; k2 < 8; k2++) v += part0[(size_t)(k2*16 + b)*4096 + n];
                g4[q4] = v;
            }
            int idx = b*1024 + hh;
            float cn = sigf(g4[1]) * cd0[idx] + sigf(g4[0]) * tanhf(g4[2]);
            float hn = sigf(g4[3]) * tanhf(cn);
            cd0[idx] = cn; hd0[idx] = hn;
        }
        gridbar();
        // ---- Phase C: layer1 gate partials from [hd0, hd1] ----
        for (int i = tid; i < 256*16; i += 256) {
            int k = i >> 4, b = i & 15, kg = kbaseA + k;
            sbuf[i] = (kg < 1024) ? hd0[b*1024 + kg] : hd1[b*1024 + kg - 1024];
        }
        __syncthreads();
        {
            const float2* vs2 = (const float2*)sbuf;
            float2 acc[8];
            #pragma unroll
            for (int bp = 0; bp < 8; bp++) acc[bp] = make_float2(0.f, 0.f);
            const float* wp = WdecT1 + (size_t)kbaseA * 4096 + nA;
            #pragma unroll 8
            for (int k = 0; k < 256; k++) {
                float w = wp[(size_t)k * 4096];
                float2 w2 = make_float2(w, w);
                #pragma unroll
                for (int bp = 0; bp < 8; bp++) acc[bp] = ffma2(w2, vs2[k*8+bp], acc[bp]);
            }
            float* pp = part1 + (size_t)(kcA*16) * 4096 + nA;
            #pragma unroll
            for (int bp = 0; bp < 8; bp++) {
                pp[(size_t)(2*bp)   * 4096] = acc[bp].x;
                pp[(size_t)(2*bp+1) * 4096] = acc[bp].y;
            }
        }
        gridbar();
        // ---- Phase D: cell1 ----
        if (gi < 16384) {
            int b = gi >> 10, hh = gi & 1023;
            float g4[4];
            #pragma unroll
            for (int q4 = 0; q4 < 4; q4++) {
                int n = q4*1024 + hh;
                float v = bias1[n];
                #pragma unroll
                for (int k2 = 0; k2 < 8; k2++) v += part1[(size_t)(k2*16 + b)*4096 + n];
                g4[q4] = v;
            }
            int idx = b*1024 + hh;
            float cn = sigf(g4[1]) * cd1[idx] + sigf(g4[0]) * tanhf(g4[2]);
            float hn = sigf(g4[3]) * tanhf(cn);
            cd1[idx] = cn; hd1[idx] = hn;
        }
        gridbar();
        // ---- Phase E: q = hd1 @ lininT ----
        if (gi < 16384) {
            int b = gi >> 10, h = gi & 1023;
            const float* wq = lininT + h;
            const float* hv = hd1 + b*1024;
            float acc = 0.f;
            #pragma unroll 8
            for (int k = 0; k < 1024; k++) acc += wq[(size_t)k * 1024] * hv[k];
            q[b*1024 + h] = acc;
        }
        gridbar();
        // ---- Phase F: attention softmax + context (blocks 0..15) ----
        if (bid < 16) {
            int b = bid;
            float* qs = sbuf;
            float* scs = sbuf + 1024;
            for (int h = tid; h < 1024; h += 256) qs[h] = q[b*1024 + h];
            __syncthreads();
            int wid = tid >> 5, lane = tid & 31;
            for (int s = wid; s < 128; s += 8) {
                const float* e = enc + ((size_t)b*128 + s) * 1024;
                float a = 0.f;
                for (int k = lane; k < 1024; k += 32) a += e[k] * qs[k];
                #pragma unroll
                for (int o = 16; o; o >>= 1) a += __shfl_xor_sync(0xffffffffu, a, o);
                if (!lane) scs[s] = a;
            }
            __syncthreads();
            if (tid < 32) {
                float m = -1e30f;
                for (int s = tid; s < 128; s += 32) m = fmaxf(m, scs[s]);
                #pragma unroll
                for (int o = 16; o; o >>= 1) m = fmaxf(m, __shfl_xor_sync(0xffffffffu, m, o));
                float sum = 0.f;
                for (int s = tid; s < 128; s += 32) { float e2 = expf(scs[s]-m); scs[s] = e2; sum += e2; }
                #pragma unroll
                for (int o = 16; o; o >>= 1) sum += __shfl_xor_sync(0xffffffffu, sum, o);
                float inv = 1.f / sum;
                for (int s = tid; s < 128; s += 32) scs[s] *= inv;
            }
            __syncthreads();
            for (int h = tid; h < 1024; h += 256) {
                float a = 0.f;
                const float* e = enc + (size_t)b*131072 + h;
                #pragma unroll 8
                for (int s = 0; s < 128; s++) a += scs[s] * e[(size_t)s*1024];
                ccv[b*1024 + h] = a;
            }
        }
        gridbar();
        // ---- Phase G: linout partials from [cc, hd1] ----
        for (int i = tid; i < 64*16; i += 256) {
            int k = i >> 4, b = i & 15, kg = kbaseG + k;
            sbuf[i] = (kg < 1024) ? ccv[b*1024 + kg] : hd1[b*1024 + kg - 1024];
        }
        __syncthreads();
        {
            const float2* vs2 = (const float2*)sbuf;
            float2 acc[8];
            #pragma unroll
            for (int bp = 0; bp < 8; bp++) acc[bp] = make_float2(0.f, 0.f);
            const float* wp = linoutT + (size_t)kbaseG * 1024 + nG;
            #pragma unroll 8
            for (int k = 0; k < 64; k++) {
                float w = wp[(size_t)k * 1024];
                float2 w2 = make_float2(w, w);
                #pragma unroll
                for (int bp = 0; bp < 8; bp++) acc[bp] = ffma2(w2, vs2[k*8+bp], acc[bp]);
            }
            float* pp = lopart + (size_t)(kcG*16) * 1024 + nG;
            #pragma unroll
            for (int bp = 0; bp < 8; bp++) {
                pp[(size_t)(2*bp)   * 1024] = acc[bp].x;
                pp[(size_t)(2*bp+1) * 1024] = acc[bp].y;
            }
        }
        gridbar();
        // ---- Phase H: opn = tanh(...) ----
        if (gi < 16384) {
            int b = gi >> 10, hh = gi & 1023;
            float v = 0.f;
            #pragma unroll
            for (int k2 = 0; k2 < 32; k2++) v += lopart[(size_t)(k2*16 + b)*1024 + hh];
            float o = tanhf(v);
            op[b*1024 + hh] = o;
            opn[((size_t)b*128 + t)*1024 + hh] = o;
        }
        gridbar();
    }
}

// ---------------- host ----------------
#define ADDRF(v) ([]{ void* q_ = nullptr; cudaGetSymbolAddress(&q_, v); return (float*)q_; }())

extern "C" void kernel_launch(void* const* d_in, const int* in_sizes, int n_in,
                              void* d_out, int out_size) {
    const float* enc_emb      = (const float*)d_in[0];
    const float* dec_emb      = (const float*)d_in[1];
    const float* enc_Wih      = (const float*)d_in[2];
    const float* enc_Whh      = (const float*)d_in[3];
    const float* enc_b        = (const float*)d_in[4];
    const float* dec_Wih0     = (const float*)d_in[5];
    const float* dec_Wih_rest = (const float*)d_in[6];
    const float* dec_Whh      = (const float*)d_in[7];
    const float* dec_b        = (const float*)d_in[8];
    const float* linin_W      = (const float*)d_in[9];
    const float* linout_W     = (const float*)d_in[10];
    const float* gen_W        = (const float*)d_in[11];
    const float* gen_b        = (const float*)d_in[12];
    const int*   inp          = (const int*)d_in[13];
    const int*   outtok       = (const int*)d_in[14];
    float* logits = (float*)d_out;

    float* xbuf0   = ADDRF(g_xbuf0);
    float* xbuf1   = ADDRF(g_xbuf1);
    float* gatesin = ADDRF(g_gatesin);
    float* WhhEncT = ADDRF(g_WhhEncT);
    float* henc    = ADDRF(g_henc);
    float* cenc    = ADDRF(g_cenc);
    float* epart   = ADDRF(g_epart);
    float* hdec    = ADDRF(g_hdec);
    float* cdec    = ADDRF(g_cdec);
    float* demb    = ADDRF(g_demb);
    float* preL0   = ADDRF(g_preL0);
    float* WdecT0  = ADDRF(g_WdecT0);
    float* WdecT1  = ADDRF(g_WdecT1);
    float* lininT  = ADDRF(g_lininT);
    float* linoutT = ADDRF(g_linoutT);
    float* op      = ADDRF(g_op);
    float* ccv     = ADDRF(g_cc);
    float* part0   = ADDRF(g_part0);
    float* part1   = ADDRF(g_part1);
    float* q       = ADDRF(g_q);
    float* lopart  = ADDRF(g_lopart);
    float* opn     = ADDRF(g_opn);

    dim3 tb(32, 8);
    // weight transposes to k-major
    for (int ld = 0; ld < 4; ld++)
        k_transpose<<<dim3(16, 64), tb>>>(enc_Whh + (size_t)ld*2048*512,
                                          WhhEncT + (size_t)ld*512*2048, 2048, 512, 512, 0);
    k_transpose<<<dim3(32, 128), tb>>>(dec_Wih0, WdecT0, 4096, 1024, 2048, 1024);
    k_transpose<<<dim3(32, 128), tb>>>(dec_Whh, WdecT0 + (size_t)1024*4096, 4096, 1024, 1024, 0);
    k_transpose<<<dim3(32, 128), tb>>>(dec_Wih_rest, WdecT1, 4096, 1024, 1024, 0);
    k_transpose<<<dim3(32, 128), tb>>>(dec_Whh + (size_t)4096*1024, WdecT1 + (size_t)1024*4096,
                                       4096, 1024, 1024, 0);
    k_transpose<<<dim3(32, 32), tb>>>(linin_W, lininT, 1024, 1024, 1024, 0);
    k_transpose<<<dim3(64, 32), tb>>>(linout_W, linoutT, 1024, 2048, 2048, 0);

    // embeddings
    k_embed_enc<<<(Bv*Sv*Hv)/256, 256>>>(enc_emb, inp, xbuf0);
    k_embed_dec<<<(Bv*Tv*Hv)/256, 256>>>(dec_emb, outtok, demb);

    // ---- encoder ----
    float* cur = xbuf0;
    float* nxt = xbuf1;
    for (int l = 0; l < 2; l++) {
        for (int d = 0; d < 2; d++)
            k_gemm<<<dim3(16, 16), 256>>>(cur, 1024,
                                          enc_Wih + (size_t)(l*2+d)*2048*1024, 1024,
                                          enc_b + (size_t)(l*2+d)*2048,
                                          gatesin + (size_t)d*2048*2048, 2048, 1024);
        k_enc_persist<<<NBLK, 256>>>(WhhEncT + (size_t)l*2*512*2048, gatesin,
                                     henc, cenc, nxt, epart,
                                     hdec + (size_t)l*16*1024, cdec + (size_t)l*16*1024);
        float* t_ = cur; cur = nxt; nxt = t_;
    }
    // enc = cur

    // ---- decoder ----
    k_gemm<<<dim3(32, 16), 256>>>(demb, 1024, dec_Wih0, 2048, dec_b, preL0, 4096, 1024);
    k_dec_persist<<<NBLK, 256>>>(WdecT0, WdecT1, lininT, linoutT, preL0, dec_b + 4096,
                                 cur, op,
                                 hdec, cdec, hdec + 16*1024, cdec + 16*1024,
                                 part0, part1, q, ccv, lopart, opn);

    // ---- generator ----
    k_gemm<<<dim3(250, 16), 256>>>(opn, 1024, gen_W, 1024, gen_b, logits, 32000, 1024);
}